// round 16
// baseline (speedup 1.0000x reference)
#include <cuda_runtime.h>
#include <cstdint>

#define NB 64
#define NO 10
#define NI 8000
#define ND 16
#define NE 8

#define ITILE 4
#define NTHR 512
#define NSTAGES (NI / ITILE)     // 2000 stages of 4 i's

#define WSTG (ITILE * NO * 512)  // 20480 B of W per stage (10 x 2048B chunks)
#define XSTG (NB * ITILE * 32)   // 8192 B of x per stage (64 x 128B chunks)
#define SLOTB (WSTG + XSTG)      // 28672 B per ring slot
#define SMEM_BYTES (3 * SLOTB)   // 86016 B dynamic

#define NBLK 148                 // 1 block/SM, one full wave
#define STEPI (NBLK * ITILE)     // i0 advance per grid-stride step = 592

// Scratch (no allocation allowed). g_s zeroed by the fused squash each pass,
// g_ticket reset by the last block -> graph replays are deterministic.
__device__ float g_s[NB * NO * ND] = {};
__device__ float g_v[NB * NO * ND] = {};
__device__ float g_vsum[NB * NO * ND] = {};
__device__ unsigned int g_ticket = 0;

// ---- f32x2 packed math (sm_10x; ptxas won't auto-fuse, must be PTX) ----
__device__ __forceinline__ unsigned long long f2mul(unsigned long long a, unsigned long long b) {
    unsigned long long d;
    asm("mul.rn.f32x2 %0, %1, %2;" : "=l"(d) : "l"(a), "l"(b));
    return d;
}
__device__ __forceinline__ unsigned long long f2fma(unsigned long long a, unsigned long long b, unsigned long long c) {
    unsigned long long d;
    asm("fma.rn.f32x2 %0, %1, %2, %3;" : "=l"(d) : "l"(a), "l"(b), "l"(c));
    return d;
}
__device__ __forceinline__ float f2hadd(unsigned long long a) {
    float lo, hi;
    asm("mov.b64 {%0, %1}, %2;" : "=f"(lo), "=f"(hi) : "l"(a));
    return lo + hi;
}

__device__ __forceinline__ uint32_t sptr(const void* p) {
    return (uint32_t)__cvta_generic_to_shared(p);
}

// ---- bulk-async copy (UBLKCP) + mbarrier helpers ----
__device__ __forceinline__ void cpbulk(uint32_t dst, const void* src, uint32_t bytes, uint32_t mbar) {
    asm volatile(
        "cp.async.bulk.shared::cluster.global.mbarrier::complete_tx::bytes [%0], [%1], %2, [%3];"
        :: "r"(dst), "l"(src), "r"(bytes), "r"(mbar) : "memory");
}
__device__ __forceinline__ void mbar_init(uint32_t mbar, uint32_t count) {
    asm volatile("mbarrier.init.shared.b64 [%0], %1;" :: "r"(mbar), "r"(count) : "memory");
}
__device__ __forceinline__ void mbar_expect_tx(uint32_t mbar, uint32_t bytes) {
    asm volatile("mbarrier.arrive.expect_tx.shared.b64 _, [%0], %1;"
                 :: "r"(mbar), "r"(bytes) : "memory");
}
__device__ __forceinline__ void mbar_wait(uint32_t mbar, uint32_t parity) {
    asm volatile(
        "{\n\t"
        ".reg .pred P;\n\t"
        "W_%=:\n\t"
        "mbarrier.try_wait.parity.acquire.cta.shared::cta.b64 P, [%0], %1, 0x989680;\n\t"
        "@!P bra W_%=;\n\t"
        "}"
        :: "r"(mbar), "r"(parity) : "memory");
}

// ---- staging descriptor: threads 0..9 copy W (per-o 2048B chunks),
// threads 10..73 copy x (per-b 128B chunks). smem slot layout:
//   [o*2048 .. ] raw W[o, i0..i0+3, :, :]  (float4 idx within (o,j): 2d+e4)
//   [WSTG + b*128 .. ] raw x[b, i0..i0+3, :]
struct BulkStager {
    const char* src;
    uint32_t dstoff, bytes;
    long step;
    bool active;

    __device__ __forceinline__ void init(int tid, int i00,
                                         const void* Wg, const void* xg) {
        active = (tid < 74);
        src = nullptr; dstoff = 0; bytes = 0; step = 0;
        if (tid < 10) {
            src    = (const char*)Wg + (size_t)tid * NI * 512 + (size_t)i00 * 512;
            dstoff = (uint32_t)tid * 2048u;
            bytes  = 2048;
            step   = (long)STEPI * 512;
        } else if (tid < 74) {
            int b  = tid - 10;
            src    = (const char*)xg + (size_t)b * NI * 32 + (size_t)i00 * 32;
            dstoff = WSTG + (uint32_t)b * 128u;
            bytes  = 128;
            step   = (long)STEPI * 32;
        }
    }
    __device__ __forceinline__ void issue(uint32_t smbase, int slot, uint32_t mbar) {
        if (active) {
            cpbulk(smbase + (uint32_t)slot * SLOTB + dstoff, src, bytes, mbar);
            src += step;
        }
    }
};

// ---- fused squash epilogue (last block), shared by all passes ----
template <int ITER>
__device__ __forceinline__ void squash_epilogue(int tid, float* __restrict__ out)
{
    __threadfence();
    __shared__ unsigned int lastFlag;
    if (tid == 0)
        lastFlag = (atomicAdd(&g_ticket, 1u) == (unsigned)(NBLK - 1)) ? 1u : 0u;
    __syncthreads();
    if (!lastFlag) return;
    __threadfence();  // acquire: all other blocks' atomics are visible

    const float prescale = (ITER == 0) ? 0.1f : 1.0f;
    #pragma unroll
    for (int k = 0; k < (NB * NO * ND) / NTHR; k++) {
        int idx = k * NTHR + tid;            // idx & 15 == d-lane
        float val = g_s[idx] * prescale;
        g_s[idx] = 0.f;
        float n2 = val * val;
        n2 += __shfl_xor_sync(0xffffffffu, n2, 8, 16);
        n2 += __shfl_xor_sync(0xffffffffu, n2, 4, 16);
        n2 += __shfl_xor_sync(0xffffffffu, n2, 2, 16);
        n2 += __shfl_xor_sync(0xffffffffu, n2, 1, 16);
        float norm  = sqrtf(n2);
        float scale = n2 / ((1.f + n2) * (norm + 1e-8f));
        float v = scale * val;
        if (ITER == 0)      { g_v[idx] = v; g_vsum[idx] = v; }
        else if (ITER == 1) { g_v[idx] = v; g_vsum[idx] += v; }
        else                { out[idx] = v; }
    }
    if (tid == 0) g_ticket = 0;  // reset for next pass / next graph replay
}

// W smem read pattern (permute-free, conflict-free):
// lane with d-index d uses sel = (d>>2)&1 and reads float4s
//   A = shW[(og*ITILE+j)*32 + 2d + sel]      (e-half = sel)
//   B = shW[(og*ITILE+j)*32 + 2d + 1-sel]    (e-half = 1-sel)
// Each quarter-warp phase covers all 32 banks (verified). The e-half swap is
// absorbed by pairing A with xP = sel ? x_hi : x_lo and B with the other.

// ============ PASS 0: (4 batch, 5 o) per thread ============
__global__ void __launch_bounds__(NTHR, 1)
pass0_kernel(const float* __restrict__ xg, const float* __restrict__ Wg,
             float* __restrict__ out)
{
    extern __shared__ char smemraw[];
    __shared__ unsigned long long mbar[3];

    const int tid  = threadIdx.x;
    const int lane = tid & 15;        // d
    const int grp  = tid >> 4;        // 0..31
    const int quad = grp >> 1;        // 0..15 -> batches 4q..4q+3
    const int ob   = (grp & 1) * 5;   // o-half base: 0 or 5
    const int sel  = (lane >> 2) & 1;
    const int idxA = 2 * lane + sel;
    const int idxB = 2 * lane + 1 - sel;

    const uint32_t smbase = sptr(smemraw);
    const uint32_t mb0 = sptr(&mbar[0]);

    if (tid == 0) {
        mbar_init(mb0, 1);
        mbar_init(mb0 + 8, 1);
        mbar_init(mb0 + 16, 1);
        asm volatile("fence.proxy.async.shared::cta;" ::: "memory");
    }
    __syncthreads();

    unsigned long long accp[4][5];
    #pragma unroll
    for (int bb = 0; bb < 4; bb++)
        #pragma unroll
        for (int o = 0; o < 5; o++) accp[bb][o] = 0ull;

    const int st0 = blockIdx.x;
    BulkStager sg;
    sg.init(tid, st0 * ITILE, Wg, xg);

    // prologue: arm + fill slots 0 and 1 (always >=2 stages remain per block)
    if (tid == 0) { mbar_expect_tx(mb0, SLOTB); mbar_expect_tx(mb0 + 8, SLOTB); }
    __syncthreads();
    sg.issue(smbase, 0, mb0);
    sg.issue(smbase, 1, mb0 + 8);

    int slot = 0, par = 0;
    for (int st = st0; st < NSTAGES; st += NBLK) {
        mbar_wait(mb0 + slot * 8, par);
        const int nslot = (slot + 2 >= 3) ? slot - 1 : slot + 2;
        const bool more = (st + 2 * NBLK < NSTAGES);
        if (more && tid == 0) mbar_expect_tx(mb0 + nslot * 8, SLOTB);
        __syncthreads();
        if (more) sg.issue(smbase, nslot, mb0 + nslot * 8);

        const ulonglong2* shWc = reinterpret_cast<const ulonglong2*>(smemraw + slot * SLOTB);
        const ulonglong2* shxc = reinterpret_cast<const ulonglong2*>(smemraw + slot * SLOTB + WSTG);

        #pragma unroll
        for (int j = 0; j < ITILE; j++) {
            ulonglong2 xP[4], xQ[4];
            #pragma unroll
            for (int bb = 0; bb < 4; bb++) {
                ulonglong2 xl = shxc[((quad * 4 + bb) * ITILE + j) * 2 + 0];  // e0..3
                ulonglong2 xh = shxc[((quad * 4 + bb) * ITILE + j) * 2 + 1];  // e4..7
                xP[bb] = sel ? xh : xl;
                xQ[bb] = sel ? xl : xh;
            }
            #pragma unroll
            for (int o = 0; o < 5; o++) {
                const int wb4 = ((ob + o) * ITILE + j) * 32;
                ulonglong2 wA = shWc[wb4 + idxA];  // e-half 'sel'
                ulonglong2 wB = shWc[wb4 + idxB];  // e-half '1-sel'
                #pragma unroll
                for (int bb = 0; bb < 4; bb++) {
                    accp[bb][o] = f2fma(wA.x, xP[bb].x, accp[bb][o]);
                    accp[bb][o] = f2fma(wA.y, xP[bb].y, accp[bb][o]);
                    accp[bb][o] = f2fma(wB.x, xQ[bb].x, accp[bb][o]);
                    accp[bb][o] = f2fma(wB.y, xQ[bb].y, accp[bb][o]);
                }
            }
        }
        slot = (slot + 1 == 3) ? 0 : slot + 1;
        if (slot == 0) par ^= 1;
    }

    #pragma unroll
    for (int bb = 0; bb < 4; bb++)
        #pragma unroll
        for (int o = 0; o < 5; o++)
            atomicAdd(&g_s[((quad * 4 + bb) * NO + ob + o) * ND + lane],
                      f2hadd(accp[bb][o]));

    squash_epilogue<0>(tid, out);
}

// ============ ROUTED PASSES (ITER 1/2): o-split + e-broadcast softmax ============
template <int ITER>
__global__ void __launch_bounds__(NTHR, 1)
pass_kernel(const float* __restrict__ xg, const float* __restrict__ Wg,
            float* __restrict__ out)
{
    extern __shared__ char smemraw[];
    __shared__ unsigned long long mbar[3];

    const int tid  = threadIdx.x;
    const int wid  = tid >> 5;        // warp 0..15
    const int l32  = tid & 31;
    const int d    = tid & 15;        // d-lane
    const int ob   = (l32 >> 4) * 5;  // o-half base: 0 or 5
    const int bq   = wid * 4;         // batch base
    const int sel  = (d >> 2) & 1;
    const int idxA = 2 * d + sel;
    const int idxB = 2 * d + 1 - sel;

    const bool s8 = (d & 8) != 0;
    const bool s4 = (d & 4) != 0;
    const bool s2 = (d & 2) != 0;

    const uint32_t smbase = sptr(smemraw);
    const uint32_t mb0 = sptr(&mbar[0]);

    if (tid == 0) {
        mbar_init(mb0, 1);
        mbar_init(mb0 + 8, 1);
        mbar_init(mb0 + 16, 1);
        asm volatile("fence.proxy.async.shared::cta;" ::: "memory");
    }
    __syncthreads();

    float vr[4][5], acc[4][5];
    {
        const float* vin = (ITER == 1) ? g_v : g_vsum;
        #pragma unroll
        for (int bb = 0; bb < 4; bb++)
            #pragma unroll
            for (int o = 0; o < 5; o++) {
                vr[bb][o] = vin[((bq + bb) * NO + ob + o) * ND + d];
                acc[bb][o] = 0.f;
            }
    }

    const int st0 = blockIdx.x;
    BulkStager sg;
    sg.init(tid, st0 * ITILE, Wg, xg);

    if (tid == 0) { mbar_expect_tx(mb0, SLOTB); mbar_expect_tx(mb0 + 8, SLOTB); }
    __syncthreads();
    sg.issue(smbase, 0, mb0);
    sg.issue(smbase, 1, mb0 + 8);

    int slot = 0, par = 0;
    for (int st = st0; st < NSTAGES; st += NBLK) {
        mbar_wait(mb0 + slot * 8, par);
        const int nslot = (slot + 2 >= 3) ? slot - 1 : slot + 2;
        const bool more = (st + 2 * NBLK < NSTAGES);
        if (more && tid == 0) mbar_expect_tx(mb0 + nslot * 8, SLOTB);
        __syncthreads();
        if (more) sg.issue(smbase, nslot, mb0 + nslot * 8);

        const ulonglong2* shWc = reinterpret_cast<const ulonglong2*>(smemraw + slot * SLOTB);
        const ulonglong2* shxc = reinterpret_cast<const ulonglong2*>(smemraw + slot * SLOTB + WSTG);

        #pragma unroll
        for (int j = 0; j < ITILE; j++) {
            ulonglong2 xP[4], xQ[4];
            #pragma unroll
            for (int bb = 0; bb < 4; bb++) {
                ulonglong2 xl = shxc[((bq + bb) * ITILE + j) * 2 + 0];  // e0..3
                ulonglong2 xh = shxc[((bq + bb) * ITILE + j) * 2 + 1];  // e4..7
                xP[bb] = sel ? xh : xl;
                xQ[bb] = sel ? xl : xh;
            }

            // u[bb][oo] for this half's 5 o's, 4 batches
            float u[4][5];
            #pragma unroll
            for (int oo = 0; oo < 5; oo++) {
                const int wb4 = ((ob + oo) * ITILE + j) * 32;
                ulonglong2 wA = shWc[wb4 + idxA];
                ulonglong2 wB = shWc[wb4 + idxB];
                #pragma unroll
                for (int bb = 0; bb < 4; bb++) {
                    unsigned long long t = f2mul(wA.x, xP[bb].x);
                    t = f2fma(wA.y, xP[bb].y, t);
                    t = f2fma(wB.x, xQ[bb].x, t);
                    t = f2fma(wB.y, xQ[bb].y, t);
                    u[bb][oo] = f2hadd(t);
                }
            }

            // routing per batch: both halves handle their own 5 o's in SIMD
            #pragma unroll
            for (int bb = 0; bb < 4; bb++) {
                float p[5];
                #pragma unroll
                for (int oo = 0; oo < 5; oo++) p[oo] = u[bb][oo] * vr[bb][oo];

                // pairing tree over 16 d-lanes, 5 arrays -> 7 SHFL
                float q0, q1, q2;
                {
                    float keep = s8 ? p[1] : p[0];
                    float send = s8 ? p[0] : p[1];
                    q0 = keep + __shfl_xor_sync(0xffffffffu, send, 8, 16);
                }
                {
                    float keep = s8 ? p[3] : p[2];
                    float send = s8 ? p[2] : p[3];
                    q1 = keep + __shfl_xor_sync(0xffffffffu, send, 8, 16);
                }
                q2 = p[4] + __shfl_xor_sync(0xffffffffu, p[4], 8, 16);
                float r0, r1;
                {
                    float keep = s4 ? q1 : q0;
                    float send = s4 ? q0 : q1;
                    r0 = keep + __shfl_xor_sync(0xffffffffu, send, 4, 16);
                }
                r1 = q2 + __shfl_xor_sync(0xffffffffu, q2, 4, 16);
                float t0;
                {
                    float keep = s2 ? r1 : r0;
                    float send = s2 ? r0 : r1;
                    t0 = keep + __shfl_xor_sync(0xffffffffu, send, 2, 16);
                }
                float a = t0 + __shfl_xor_sync(0xffffffffu, t0, 1, 16);
                // lane holds complete a for o = s2 ? 4 : 2*s4+s8 (local)

                // exp at every lane (logits tiny -> no max subtraction)
                float e = __expf(a);

                // broadcast the 5 e's from owner lanes (this half's o0..o4)
                float e0 = __shfl_sync(0xffffffffu, e, 0, 16);
                float e1 = __shfl_sync(0xffffffffu, e, 8, 16);
                float e2 = __shfl_sync(0xffffffffu, e, 4, 16);
                float e3 = __shfl_sync(0xffffffffu, e, 12, 16);
                float e4 = __shfl_sync(0xffffffffu, e, 2, 16);

                // denominator: this half's sum + other half's sum (xor16)
                float mh = ((e0 + e1) + (e2 + e3)) + e4;
                float m  = mh + __shfl_xor_sync(0xffffffffu, mh, 16);
                float rinv = __fdividef(1.f, m);

                acc[bb][0] = fmaf(e0 * rinv, u[bb][0], acc[bb][0]);
                acc[bb][1] = fmaf(e1 * rinv, u[bb][1], acc[bb][1]);
                acc[bb][2] = fmaf(e2 * rinv, u[bb][2], acc[bb][2]);
                acc[bb][3] = fmaf(e3 * rinv, u[bb][3], acc[bb][3]);
                acc[bb][4] = fmaf(e4 * rinv, u[bb][4], acc[bb][4]);
            }
        }
        slot = (slot + 1 == 3) ? 0 : slot + 1;
        if (slot == 0) par ^= 1;
    }

    #pragma unroll
    for (int bb = 0; bb < 4; bb++)
        #pragma unroll
        for (int oo = 0; oo < 5; oo++)
            atomicAdd(&g_s[((bq + bb) * NO + ob + oo) * ND + d], acc[bb][oo]);

    squash_epilogue<ITER>(tid, out);
}

extern "C" void kernel_launch(void* const* d_in, const int* in_sizes, int n_in,
                              void* d_out, int out_size)
{
    const float* x = (const float*)d_in[0];  // [64, 8000, 8]
    const float* W = (const float*)d_in[1];  // [10, 8000, 16, 8]
    float* out = (float*)d_out;              // [64, 10, 16]

    // dynamic smem opt-in (host attribute set; idempotent, capture-safe)
    cudaFuncSetAttribute(pass0_kernel,
                         cudaFuncAttributeMaxDynamicSharedMemorySize, SMEM_BYTES);
    cudaFuncSetAttribute(pass_kernel<1>,
                         cudaFuncAttributeMaxDynamicSharedMemorySize, SMEM_BYTES);
    cudaFuncSetAttribute(pass_kernel<2>,
                         cudaFuncAttributeMaxDynamicSharedMemorySize, SMEM_BYTES);

    pass0_kernel<<<NBLK, NTHR, SMEM_BYTES>>>(x, W, out);
    pass_kernel<1><<<NBLK, NTHR, SMEM_BYTES>>>(x, W, out);
    pass_kernel<2><<<NBLK, NTHR, SMEM_BYTES>>>(x, W, out);
}

// round 17
// speedup vs baseline: 1.0397x; 1.0397x over previous
#include <cuda_runtime.h>
#include <cstdint>

#define NB 64
#define NO 10
#define NI 8000
#define ND 16
#define NE 8

#define ITILE 4
#define NTHR 512
#define NSTAGES (NI / ITILE)     // 2000 stages of 4 i's

#define NWITEM (ITILE * NO * 32) // 1280 W float4 per stage (permuted layout)
#define WBUFB (NWITEM * 16)      // 20480 B per W buffer
#define XSTG (NB * ITILE * 32)   // 8192 B of x per stage (64 x 128B bulk chunks)
#define SMEM_BYTES (3 * WBUFB + 3 * XSTG)  // 86016 B dynamic

#define NBLK 148                 // 1 block/SM, one full wave
#define STEPI (NBLK * ITILE)     // i0 advance per grid-stride step = 592

// Scratch (no allocation allowed). g_s zeroed by the fused squash each pass,
// g_ticket reset by the last block -> graph replays are deterministic.
__device__ float g_s[NB * NO * ND] = {};
__device__ float g_v[NB * NO * ND] = {};
__device__ float g_vsum[NB * NO * ND] = {};
__device__ unsigned int g_ticket = 0;

// ---- f32x2 packed math (sm_10x; ptxas won't auto-fuse, must be PTX) ----
__device__ __forceinline__ unsigned long long f2mul(unsigned long long a, unsigned long long b) {
    unsigned long long d;
    asm("mul.rn.f32x2 %0, %1, %2;" : "=l"(d) : "l"(a), "l"(b));
    return d;
}
__device__ __forceinline__ unsigned long long f2fma(unsigned long long a, unsigned long long b, unsigned long long c) {
    unsigned long long d;
    asm("fma.rn.f32x2 %0, %1, %2, %3;" : "=l"(d) : "l"(a), "l"(b), "l"(c));
    return d;
}
__device__ __forceinline__ float f2hadd(unsigned long long a) {
    float lo, hi;
    asm("mov.b64 {%0, %1}, %2;" : "=f"(lo), "=f"(hi) : "l"(a));
    return lo + hi;
}

__device__ __forceinline__ uint32_t sptr(const void* p) {
    return (uint32_t)__cvta_generic_to_shared(p);
}

// ---- cp.async (LDGSTS) helpers (W staging) ----
__device__ __forceinline__ void cp16(uint32_t dst, const void* src) {
    asm volatile("cp.async.ca.shared.global [%0], [%1], 16;" :: "r"(dst), "l"(src));
}
__device__ __forceinline__ void cp_commit() { asm volatile("cp.async.commit_group;"); }
template <int N>
__device__ __forceinline__ void cp_wait() { asm volatile("cp.async.wait_group %0;" :: "n"(N)); }

// ---- bulk-async copy (UBLKCP) + mbarrier helpers (x staging) ----
__device__ __forceinline__ void cpbulk(uint32_t dst, const void* src, uint32_t bytes, uint32_t mbar) {
    asm volatile(
        "cp.async.bulk.shared::cluster.global.mbarrier::complete_tx::bytes [%0], [%1], %2, [%3];"
        :: "r"(dst), "l"(src), "r"(bytes), "r"(mbar) : "memory");
}
__device__ __forceinline__ void mbar_init(uint32_t mbar, uint32_t count) {
    asm volatile("mbarrier.init.shared.b64 [%0], %1;" :: "r"(mbar), "r"(count) : "memory");
}
__device__ __forceinline__ void mbar_expect_tx(uint32_t mbar, uint32_t bytes) {
    asm volatile("mbarrier.arrive.expect_tx.shared.b64 _, [%0], %1;"
                 :: "r"(mbar), "r"(bytes) : "memory");
}
__device__ __forceinline__ void mbar_wait(uint32_t mbar, uint32_t parity) {
    asm volatile(
        "{\n\t"
        ".reg .pred P;\n\t"
        "W_%=:\n\t"
        "mbarrier.try_wait.parity.acquire.cta.shared::cta.b64 P, [%0], %1, 0x989680;\n\t"
        "@!P bra W_%=;\n\t"
        "}"
        :: "r"(mbar), "r"(parity) : "memory");
}

// ---- W staging (per-thread, permuted): 1280 items, 512 threads ----
// shW per (j,o): 32 float4, idx qs = e4*16 + d  (conflict-free LDS.128 reads)
// cpA: item tid. cpB: item tid+512. cpC: tid<256 -> item tid+1024.
struct WStager {
    const float4 *sA, *sB, *sC;
    uint32_t dA, dB, dC;
    bool hasC;

    __device__ __forceinline__ void initW(int t, int i00, const float4* Wf4,
                                          uint32_t swbase,
                                          const float4*& src, uint32_t& dst) {
        int j  = t / (NO * 32);
        int r  = t - j * (NO * 32);
        int o  = r >> 5;
        int qg = r & 31;                       // global: d*2 + e4
        int qs = ((qg & 1) << 4) | (qg >> 1);  // shared: e4*16 + d
        src = Wf4 + ((size_t)o * NI + i00 + j) * 32 + qg;
        dst = swbase + (uint32_t)((j * NO + o) * 32 + qs) * 16u;
    }
    __device__ __forceinline__ void init(int tid, int i00,
                                         const float4* Wf4, uint32_t swbase) {
        initW(tid,       i00, Wf4, swbase, sA, dA);
        initW(tid + 512, i00, Wf4, swbase, sB, dB);
        hasC = (tid < 256);
        if (hasC) initW(tid + 1024, i00, Wf4, swbase, sC, dC);
        else { sC = Wf4; dC = swbase; }
    }
    __device__ __forceinline__ void issue(int ib) {
        cp16(dA + (uint32_t)ib * WBUFB, sA);  sA += 32 * STEPI;
        cp16(dB + (uint32_t)ib * WBUFB, sB);  sB += 32 * STEPI;
        if (hasC) { cp16(dC + (uint32_t)ib * WBUFB, sC); sC += 32 * STEPI; }
        cp_commit();
    }
};

// ---- x staging (bulk): 64 copies of 128B per stage, threads 0..63 ----
// slot layout (raw gmem order): b*128 + j*32 + q*16
struct XStager {
    const char* src;
    uint32_t dstoff;
    bool active;
    __device__ __forceinline__ void init(int tid, int i00, const void* xg) {
        active = (tid < NB);
        src = nullptr; dstoff = 0;
        if (active) {
            src    = (const char*)xg + (size_t)tid * NI * 32 + (size_t)i00 * 32;
            dstoff = (uint32_t)tid * 128u;
        }
    }
    __device__ __forceinline__ void issue(uint32_t sxb, int slot, uint32_t mbar) {
        if (active) {
            cpbulk(sxb + (uint32_t)slot * XSTG + dstoff, src, 128u, mbar);
            src += (long)STEPI * 32;
        }
    }
};

// ---- fused squash epilogue (last block), shared by all passes ----
template <int ITER>
__device__ __forceinline__ void squash_epilogue(int tid, float* __restrict__ out)
{
    __threadfence();
    __shared__ unsigned int lastFlag;
    if (tid == 0)
        lastFlag = (atomicAdd(&g_ticket, 1u) == (unsigned)(NBLK - 1)) ? 1u : 0u;
    __syncthreads();
    if (!lastFlag) return;
    __threadfence();  // acquire: all other blocks' atomics are visible

    const float prescale = (ITER == 0) ? 0.1f : 1.0f;
    #pragma unroll
    for (int k = 0; k < (NB * NO * ND) / NTHR; k++) {
        int idx = k * NTHR + tid;            // idx & 15 == d-lane
        float val = g_s[idx] * prescale;
        g_s[idx] = 0.f;
        float n2 = val * val;
        n2 += __shfl_xor_sync(0xffffffffu, n2, 8, 16);
        n2 += __shfl_xor_sync(0xffffffffu, n2, 4, 16);
        n2 += __shfl_xor_sync(0xffffffffu, n2, 2, 16);
        n2 += __shfl_xor_sync(0xffffffffu, n2, 1, 16);
        float norm  = sqrtf(n2);
        float scale = n2 / ((1.f + n2) * (norm + 1e-8f));
        float v = scale * val;
        if (ITER == 0)      { g_v[idx] = v; g_vsum[idx] = v; }
        else if (ITER == 1) { g_v[idx] = v; g_vsum[idx] += v; }
        else                { out[idx] = v; }
    }
    if (tid == 0) g_ticket = 0;  // reset for next pass / next graph replay
}

// ============ PASS 0: (4 batch, 5 o) per thread ============
__global__ void __launch_bounds__(NTHR, 1)
pass0_kernel(const float* __restrict__ xg, const float* __restrict__ Wg,
             float* __restrict__ out)
{
    extern __shared__ char smemraw[];        // [3*WBUFB W | 3*XSTG x]
    __shared__ unsigned long long mbar[3];
    char* shWr = smemraw;
    char* shxr = smemraw + 3 * WBUFB;

    const int tid  = threadIdx.x;
    const int lane = tid & 15;        // d
    const int grp  = tid >> 4;        // 0..31
    const int quad = grp >> 1;        // 0..15 -> batches 4q..4q+3
    const int ob   = (grp & 1) * 5;   // o-half base: 0 or 5

    const uint32_t sxb = sptr(shxr);
    const uint32_t mb0 = sptr(&mbar[0]);

    if (tid == 0) {
        mbar_init(mb0, 1);
        mbar_init(mb0 + 8, 1);
        mbar_init(mb0 + 16, 1);
        asm volatile("fence.proxy.async.shared::cta;" ::: "memory");
    }
    __syncthreads();

    unsigned long long accp[4][5];
    #pragma unroll
    for (int bb = 0; bb < 4; bb++)
        #pragma unroll
        for (int o = 0; o < 5; o++) accp[bb][o] = 0ull;

    const float4* Wf4 = (const float4*)Wg;
    const int st0 = blockIdx.x;

    WStager wg;
    wg.init(tid, st0 * ITILE, Wf4, sptr(shWr));
    XStager xs;
    xs.init(tid, st0 * ITILE, xg);

    // prologue: arm x slots 0,1; fill both (every block has >=2 stages)
    if (tid == 0) { mbar_expect_tx(mb0, XSTG); mbar_expect_tx(mb0 + 8, XSTG); }
    __syncthreads();
    wg.issue(0);  xs.issue(sxb, 0, mb0);
    wg.issue(1);  xs.issue(sxb, 1, mb0 + 8);

    int slot = 0, par = 0;
    for (int st = st0; st < NSTAGES; st += NBLK) {
        cp_wait<1>();                    // this slot's W group complete
        mbar_wait(mb0 + slot * 8, par);  // this slot's x complete
        const int nslot = (slot + 2 >= 3) ? slot - 1 : slot + 2;
        const bool more = (st + 2 * NBLK < NSTAGES);
        if (more && tid == 0) mbar_expect_tx(mb0 + nslot * 8, XSTG);
        __syncthreads();
        if (more) { wg.issue(nslot); xs.issue(sxb, nslot, mb0 + nslot * 8); }
        else cp_commit();

        const ulonglong2* shWc = reinterpret_cast<const ulonglong2*>(shWr + slot * WBUFB);
        const ulonglong2* shxc = reinterpret_cast<const ulonglong2*>(shxr + slot * XSTG);

        #pragma unroll
        for (int j = 0; j < ITILE; j++) {
            ulonglong2 xa[4], xb[4];
            #pragma unroll
            for (int bb = 0; bb < 4; bb++) {
                xa[bb] = shxc[((quad * 4 + bb) * ITILE + j) * 2 + 0];  // e0..3
                xb[bb] = shxc[((quad * 4 + bb) * ITILE + j) * 2 + 1];  // e4..7
            }
            #pragma unroll
            for (int o = 0; o < 5; o++) {
                const int og = ob + o;
                ulonglong2 wa = shWc[(j * NO + og) * 32 + lane];       // e0..3
                ulonglong2 wb = shWc[(j * NO + og) * 32 + 16 + lane];  // e4..7
                #pragma unroll
                for (int bb = 0; bb < 4; bb++) {
                    accp[bb][o] = f2fma(wa.x, xa[bb].x, accp[bb][o]);
                    accp[bb][o] = f2fma(wa.y, xa[bb].y, accp[bb][o]);
                    accp[bb][o] = f2fma(wb.x, xb[bb].x, accp[bb][o]);
                    accp[bb][o] = f2fma(wb.y, xb[bb].y, accp[bb][o]);
                }
            }
        }
        slot = (slot + 1 == 3) ? 0 : slot + 1;
        if (slot == 0) par ^= 1;
    }

    #pragma unroll
    for (int bb = 0; bb < 4; bb++)
        #pragma unroll
        for (int o = 0; o < 5; o++)
            atomicAdd(&g_s[((quad * 4 + bb) * NO + ob + o) * ND + lane],
                      f2hadd(accp[bb][o]));

    squash_epilogue<0>(tid, out);
}

// ============ ROUTED PASSES (ITER 1/2): o-split + e-broadcast softmax ============
// Warp = 4 batches. Half-warp selects o-half: lanes 0-15 -> o in [0,5),
// lanes 16-31 -> o in [5,10); d = lane & 15. Pairing tree leaves lane l
// holding the complete agreement sum for o(l) = s2 ? 4 : 2*s4+s8; owners
// {0,8,4,12,2} hold o0..o4. Softmax via owner-e broadcasts + one xor16.
template <int ITER>
__global__ void __launch_bounds__(NTHR, 1)
pass_kernel(const float* __restrict__ xg, const float* __restrict__ Wg,
            float* __restrict__ out)
{
    extern __shared__ char smemraw[];
    __shared__ unsigned long long mbar[3];
    char* shWr = smemraw;
    char* shxr = smemraw + 3 * WBUFB;

    const int tid  = threadIdx.x;
    const int wid  = tid >> 5;        // warp 0..15
    const int l32  = tid & 31;
    const int d    = tid & 15;        // d-lane
    const int ob   = (l32 >> 4) * 5;  // o-half base: 0 or 5
    const int bq   = wid * 4;         // batch base

    const bool s8 = (d & 8) != 0;
    const bool s4 = (d & 4) != 0;
    const bool s2 = (d & 2) != 0;

    const uint32_t sxb = sptr(shxr);
    const uint32_t mb0 = sptr(&mbar[0]);

    if (tid == 0) {
        mbar_init(mb0, 1);
        mbar_init(mb0 + 8, 1);
        mbar_init(mb0 + 16, 1);
        asm volatile("fence.proxy.async.shared::cta;" ::: "memory");
    }
    __syncthreads();

    float vr[4][5], acc[4][5];
    {
        const float* vin = (ITER == 1) ? g_v : g_vsum;
        #pragma unroll
        for (int bb = 0; bb < 4; bb++)
            #pragma unroll
            for (int o = 0; o < 5; o++) {
                vr[bb][o] = vin[((bq + bb) * NO + ob + o) * ND + d];
                acc[bb][o] = 0.f;
            }
    }

    const float4* Wf4 = (const float4*)Wg;
    const int st0 = blockIdx.x;

    WStager wg;
    wg.init(tid, st0 * ITILE, Wf4, sptr(shWr));
    XStager xs;
    xs.init(tid, st0 * ITILE, xg);

    if (tid == 0) { mbar_expect_tx(mb0, XSTG); mbar_expect_tx(mb0 + 8, XSTG); }
    __syncthreads();
    wg.issue(0);  xs.issue(sxb, 0, mb0);
    wg.issue(1);  xs.issue(sxb, 1, mb0 + 8);

    int slot = 0, par = 0;
    for (int st = st0; st < NSTAGES; st += NBLK) {
        cp_wait<1>();
        mbar_wait(mb0 + slot * 8, par);
        const int nslot = (slot + 2 >= 3) ? slot - 1 : slot + 2;
        const bool more = (st + 2 * NBLK < NSTAGES);
        if (more && tid == 0) mbar_expect_tx(mb0 + nslot * 8, XSTG);
        __syncthreads();
        if (more) { wg.issue(nslot); xs.issue(sxb, nslot, mb0 + nslot * 8); }
        else cp_commit();

        const ulonglong2* shWc = reinterpret_cast<const ulonglong2*>(shWr + slot * WBUFB);
        const ulonglong2* shxc = reinterpret_cast<const ulonglong2*>(shxr + slot * XSTG);

        #pragma unroll
        for (int j = 0; j < ITILE; j++) {
            ulonglong2 xa[4], xb[4];
            #pragma unroll
            for (int bb = 0; bb < 4; bb++) {
                xa[bb] = shxc[((bq + bb) * ITILE + j) * 2 + 0];  // e0..3
                xb[bb] = shxc[((bq + bb) * ITILE + j) * 2 + 1];  // e4..7
            }

            // u[bb][oo] for this half's 5 o's, 4 batches
            float u[4][5];
            #pragma unroll
            for (int oo = 0; oo < 5; oo++) {
                const int og = ob + oo;
                ulonglong2 wa = shWc[(j * NO + og) * 32 + d];
                ulonglong2 wb = shWc[(j * NO + og) * 32 + 16 + d];
                #pragma unroll
                for (int bb = 0; bb < 4; bb++) {
                    unsigned long long t = f2mul(wa.x, xa[bb].x);
                    t = f2fma(wa.y, xa[bb].y, t);
                    t = f2fma(wb.x, xb[bb].x, t);
                    t = f2fma(wb.y, xb[bb].y, t);
                    u[bb][oo] = f2hadd(t);
                }
            }

            // routing per batch: both halves handle their own 5 o's in SIMD
            #pragma unroll
            for (int bb = 0; bb < 4; bb++) {
                float p[5];
                #pragma unroll
                for (int oo = 0; oo < 5; oo++) p[oo] = u[bb][oo] * vr[bb][oo];

                // pairing tree over 16 d-lanes, 5 arrays -> 7 SHFL
                float q0, q1, q2;
                {
                    float keep = s8 ? p[1] : p[0];
                    float send = s8 ? p[0] : p[1];
                    q0 = keep + __shfl_xor_sync(0xffffffffu, send, 8, 16);
                }
                {
                    float keep = s8 ? p[3] : p[2];
                    float send = s8 ? p[2] : p[3];
                    q1 = keep + __shfl_xor_sync(0xffffffffu, send, 8, 16);
                }
                q2 = p[4] + __shfl_xor_sync(0xffffffffu, p[4], 8, 16);
                float r0, r1;
                {
                    float keep = s4 ? q1 : q0;
                    float send = s4 ? q0 : q1;
                    r0 = keep + __shfl_xor_sync(0xffffffffu, send, 4, 16);
                }
                r1 = q2 + __shfl_xor_sync(0xffffffffu, q2, 4, 16);
                float t0;
                {
                    float keep = s2 ? r1 : r0;
                    float send = s2 ? r0 : r1;
                    t0 = keep + __shfl_xor_sync(0xffffffffu, send, 2, 16);
                }
                float a = t0 + __shfl_xor_sync(0xffffffffu, t0, 1, 16);
                // lane holds complete a for o = s2 ? 4 : 2*s4+s8 (local)

                // exp at every lane (logits tiny -> no max subtraction)
                float e = __expf(a);

                // broadcast the 5 e's from owner lanes (this half's o0..o4)
                float e0 = __shfl_sync(0xffffffffu, e, 0, 16);
                float e1 = __shfl_sync(0xffffffffu, e, 8, 16);
                float e2 = __shfl_sync(0xffffffffu, e, 4, 16);
                float e3 = __shfl_sync(0xffffffffu, e, 12, 16);
                float e4 = __shfl_sync(0xffffffffu, e, 2, 16);

                // denominator: this half's sum + other half's sum (xor16)
                float mh = ((e0 + e1) + (e2 + e3)) + e4;
                float m  = mh + __shfl_xor_sync(0xffffffffu, mh, 16);
                float rinv = __fdividef(1.f, m);

                acc[bb][0] = fmaf(e0 * rinv, u[bb][0], acc[bb][0]);
                acc[bb][1] = fmaf(e1 * rinv, u[bb][1], acc[bb][1]);
                acc[bb][2] = fmaf(e2 * rinv, u[bb][2], acc[bb][2]);
                acc[bb][3] = fmaf(e3 * rinv, u[bb][3], acc[bb][3]);
                acc[bb][4] = fmaf(e4 * rinv, u[bb][4], acc[bb][4]);
            }
        }
        slot = (slot + 1 == 3) ? 0 : slot + 1;
        if (slot == 0) par ^= 1;
    }

    #pragma unroll
    for (int bb = 0; bb < 4; bb++)
        #pragma unroll
        for (int oo = 0; oo < 5; oo++)
            atomicAdd(&g_s[((bq + bb) * NO + ob + oo) * ND + d], acc[bb][oo]);

    squash_epilogue<ITER>(tid, out);
}

extern "C" void kernel_launch(void* const* d_in, const int* in_sizes, int n_in,
                              void* d_out, int out_size)
{
    const float* x = (const float*)d_in[0];  // [64, 8000, 8]
    const float* W = (const float*)d_in[1];  // [10, 8000, 16, 8]
    float* out = (float*)d_out;              // [64, 10, 16]

    // dynamic smem opt-in (host attribute set; idempotent, capture-safe)
    cudaFuncSetAttribute(pass0_kernel,
                         cudaFuncAttributeMaxDynamicSharedMemorySize, SMEM_BYTES);
    cudaFuncSetAttribute(pass_kernel<1>,
                         cudaFuncAttributeMaxDynamicSharedMemorySize, SMEM_BYTES);
    cudaFuncSetAttribute(pass_kernel<2>,
                         cudaFuncAttributeMaxDynamicSharedMemorySize, SMEM_BYTES);

    pass0_kernel<<<NBLK, NTHR, SMEM_BYTES>>>(x, W, out);
    pass_kernel<1><<<NBLK, NTHR, SMEM_BYTES>>>(x, W, out);
    pass_kernel<2><<<NBLK, NTHR, SMEM_BYTES>>>(x, W, out);
}